// round 8
// baseline (speedup 1.0000x reference)
#include <cuda_runtime.h>
#include <cuda_bf16.h>
#include <math.h>
#include <stdint.h>

// Problem constants (fixed by the reference)
#define NN 50000
#define NE 600000
#define NG 64
#define DH 128
#define DLAT 64

// GEMM factorization: feat@W = h@Wh + agg@W1 + amp*(agg@W2) + att*(agg@W3)
#define KH2 64          // h image packed pairs per row (128 cols)
#define KA2 256         // agg image packed pairs per row (512 cols)
#define NJ  40          // jobs per block: 8 h-jobs + 32 agg-jobs (k16 each)
#define WLAYER 212992   // u32 per layer W image

// ---------------- device scratch (no allocation allowed) -------------------
__device__ int   g_deg[NN];
__device__ int   g_off[NN + 1];
__device__ int   g_cur[NN];
__device__ int   g_csr[NE];
__device__ int   g_bsum[64];
__device__ float g_delta[1];
__device__ float g_h0[(size_t)NN * DH];
__device__ float g_h1[(size_t)NN * DH];
__device__ unsigned g_Hh[(size_t)NN * KH2];   // split h image hi
__device__ unsigned g_Hl[(size_t)NN * KH2];
__device__ unsigned g_Agh[(size_t)NN * KA2];  // split agg image hi
__device__ unsigned g_Agl[(size_t)NN * KA2];
__device__ unsigned g_W[3 * WLAYER];          // packed W images
__device__ float g_pool[NG * DH];

// ---------------- helpers ----------------------------------------------------
__device__ __forceinline__ void split_pair(float f0, float f1,
                                           unsigned& hi, unsigned& lo) {
    __nv_bfloat16 h0 = __float2bfloat16_rn(f0);
    __nv_bfloat16 h1 = __float2bfloat16_rn(f1);
    float r0 = f0 - __bfloat162float(h0);
    float r1 = f1 - __bfloat162float(h1);
    __nv_bfloat162 H; H.x = h0; H.y = h1;
    __nv_bfloat162 L = __floats2bfloat162_rn(r0, r1);
    hi = *reinterpret_cast<unsigned*>(&H);
    lo = *reinterpret_cast<unsigned*>(&L);
}

__device__ __forceinline__ void mma_bf16(float* d, const unsigned* a,
                                         const unsigned* b) {
    asm volatile(
        "mma.sync.aligned.m16n8k16.row.col.f32.bf16.bf16.f32 "
        "{%0,%1,%2,%3}, {%4,%5,%6,%7}, {%8,%9}, {%0,%1,%2,%3};\n"
        : "+f"(d[0]), "+f"(d[1]), "+f"(d[2]), "+f"(d[3])
        : "r"(a[0]), "r"(a[1]), "r"(a[2]), "r"(a[3]), "r"(b[0]), "r"(b[1]));
}

__device__ __forceinline__ void ldsm4(unsigned& r0, unsigned& r1,
                                      unsigned& r2, unsigned& r3, uint32_t a) {
    asm volatile("ldmatrix.sync.aligned.m8n8.x4.shared.b16 {%0,%1,%2,%3}, [%4];"
                 : "=r"(r0), "=r"(r1), "=r"(r2), "=r"(r3) : "r"(a));
}

__device__ __forceinline__ uint32_t smem_u32(const void* p) {
    uint32_t a;
    asm("{ .reg .u64 t; cvta.to.shared.u64 t, %1; cvt.u32.u64 %0, t; }"
        : "=r"(a) : "l"(p));
    return a;
}
__device__ __forceinline__ void cp16(uint32_t dst, const void* src) {
    asm volatile("cp.async.cg.shared.global [%0], [%1], 16;"
                 :: "r"(dst), "l"(src));
}
#define CP_COMMIT() asm volatile("cp.async.commit_group;" ::: "memory")
#define CP_WAIT2()  asm volatile("cp.async.wait_group 2;" ::: "memory")

// ---------------- graph prep ----------------------------------------------
__global__ void hist_kernel(const int* __restrict__ ei) {
    int e = blockIdx.x * blockDim.x + threadIdx.x;
    int stride = gridDim.x * blockDim.x;
    for (; e < NE; e += stride) atomicAdd(&g_deg[ei[NE + e]], 1);
}

// multi-block exclusive scan of g_deg -> g_off
__global__ void scan1_kernel() {
    __shared__ int sh[1024];
    int b = blockIdx.x, t = threadIdx.x;
    int i = b * 1024 + t;
    int v = (i < NN) ? g_deg[i] : 0;
    sh[t] = v;
    __syncthreads();
    #pragma unroll
    for (int s = 1; s < 1024; s <<= 1) {
        int add = (t >= s) ? sh[t - s] : 0;
        __syncthreads();
        sh[t] += add;
        __syncthreads();
    }
    if (i < NN) g_off[i] = sh[t] - v;   // exclusive within block
    if (t == 1023) g_bsum[b] = sh[1023];
}
__global__ void scan2_kernel(int nblk) {
    if (threadIdx.x == 0) {
        int c = 0;
        for (int b = 0; b < nblk; b++) { int s = g_bsum[b]; g_bsum[b] = c; c += s; }
        g_off[NN] = c;
    }
}
__global__ void scan3_kernel() {
    int b = blockIdx.x;
    int i = b * 1024 + threadIdx.x;
    if (i < NN) g_off[i] += g_bsum[b];
}

__global__ void scatter_kernel(const int* __restrict__ ei) {
    int e = blockIdx.x * blockDim.x + threadIdx.x;
    int stride = gridDim.x * blockDim.x;
    for (; e < NE; e += stride) {
        int dst = ei[NE + e];
        int pos = g_off[dst] + atomicAdd(&g_cur[dst], 1);
        g_csr[pos] = ei[e];
    }
}

__global__ void delta_kernel() {
    int i = blockIdx.x * blockDim.x + threadIdx.x;
    int stride = gridDim.x * blockDim.x;
    float s = 0.f;
    for (; i < NN; i += stride) s += logf((float)g_deg[i] + 1.f);
    #pragma unroll
    for (int o = 16; o > 0; o >>= 1) s += __shfl_down_sync(0xffffffffu, s, o);
    __shared__ float sh[32];
    int lane = threadIdx.x & 31, wid = threadIdx.x >> 5;
    if (lane == 0) sh[wid] = s;
    __syncthreads();
    if (wid == 0) {
        float v = (lane < (int)(blockDim.x >> 5)) ? sh[lane] : 0.f;
        #pragma unroll
        for (int o = 16; o > 0; o >>= 1) v += __shfl_down_sync(0xffffffffu, v, o);
        if (lane == 0) atomicAdd(&g_delta[0], v);
    }
}

// ---------------- W pre-pack --------------------------------------------------
// Per layer: h-jobs: 8 chunks of [hi 128n x 8][lo 128n x 8] (2048 u32 each);
// agg-jobs: 32 chunks x 3 matrices x 2048 u32, base 16384, chunk stride 6144.
__global__ void wsplit_kernel(const float* __restrict__ W,
                              unsigned* __restrict__ wdst) {
    int i = blockIdx.x * blockDim.x + threadIdx.x;
    if (i >= 832 * 128) return;
    int kr2 = i >> 7;
    int n = i & 127;
    int kr = 2 * kr2;
    unsigned hi, lo;
    split_pair(W[(size_t)kr * DH + n], W[(size_t)(kr + 1) * DH + n], hi, lo);
    int base, loc;
    if (kr2 < 64) {
        int ch = kr2 >> 3; loc = kr2 & 7;
        base = ch * 2048;
    } else {
        int p = kr2 - 64;
        int w = p >> 8;
        int q = p & 255;
        int ch = q >> 3; loc = q & 7;
        base = 16384 + ch * 6144 + w * 2048;
    }
    wdst[base + n * 8 + loc] = hi;
    wdst[base + 1024 + n * 8 + loc] = lo;
}

__global__ void xsplit_kernel(const float* __restrict__ x) {
    int i = blockIdx.x * blockDim.x + threadIdx.x;
    if (i >= NN * KH2) return;
    int n = i >> 6, p = i & 63;
    unsigned hi, lo;
    split_pair(x[(size_t)n * DH + 2 * p], x[(size_t)n * DH + 2 * p + 1], hi, lo);
    g_Hh[i] = hi;
    g_Hl[i] = lo;
}

// ---------------- aggregation -> split agg image (512 cols) ------------------
__global__ __launch_bounds__(128) void agg_kernel(const float* __restrict__ h) {
    int n = blockIdx.x;
    int t = threadIdx.x;
    int beg = g_off[n], end = g_off[n + 1];
    int d = end - beg;
    float s = 0.f, ss = 0.f;
    float mx = __int_as_float(0xff800000);
    float mn = __int_as_float(0x7f800000);
    __shared__ int ssrc[128];
    for (int base = beg; base < end; base += 128) {
        int cnt = min(128, end - base);
        if (t < cnt) ssrc[t] = g_csr[base + t];
        __syncthreads();
        #pragma unroll 4
        for (int i = 0; i < cnt; i++) {
            float m = h[(size_t)ssrc[i] * DH + t];
            s += m; ss += m * m;
            mx = fmaxf(mx, m); mn = fminf(mn, m);
        }
        __syncthreads();
    }
    float cntf = fmaxf((float)d, 1.f);
    float mean = s / cntf;
    float var = fmaxf(ss / cntf - mean * mean, 0.f);
    float stdv = sqrtf(var + 1e-5f);
    if (d == 0) { mx = 0.f; mn = 0.f; }

    __shared__ float sf[512];
    sf[t] = mean;
    sf[128 + t] = mx;
    sf[256 + t] = mn;
    sf[384 + t] = stdv;
    __syncthreads();

    size_t rowb = (size_t)n * KA2;
    #pragma unroll
    for (int p = t; p < KA2; p += 128) {
        unsigned hi, lo;
        split_pair(sf[2 * p], sf[2 * p + 1], hi, lo);
        g_Agh[rowb + p] = hi;
        g_Agl[rowb + p] = lo;
    }
}

// ---------------- factorized bf16x3 GEMM (4-stage cp.async, ldmatrix) --------
// smem per stage (u32): A_h[96][12] @0, A_l[96][12] @1152,
//                       B w0..2 x {hi,lo}[128][12] @2304 (w*3072, lo +1536)
#define BMR 96
#define STGU 11520
#define NSTG 4
#define SMEM_BYTES (NSTG * STGU * 4)

__global__ __launch_bounds__(384, 1) void gemm_fact_kernel(
        const unsigned* __restrict__ Wimg, const float* __restrict__ bias,
        float* __restrict__ hout, int write_split) {
    extern __shared__ unsigned smem_u[];
    const uint32_t sb = smem_u32(smem_u);

    const int tid = threadIdx.x;
    const int lane = tid & 31;
    const int wid = tid >> 5;
    const int warp_m = wid >> 2;    // 0..2 (32 rows each)
    const int warp_n = wid & 3;     // 0..3 (32 cols each)
    const int lr = lane >> 2;       // 0..7
    const int lc = lane & 3;        // 0..3
    const int row0 = blockIdx.x * BMR;

    // ldmatrix per-lane geometry (same mapping as validated R7 kernel)
    const int lg = lane >> 3;
    const int l8 = lane & 7;
    const int a_row = ((lg & 1) << 3) + l8;
    const int a_col = (lg >> 1) << 2;
    const int b_row = ((lg >> 1) << 3) + l8;
    const int b_col = (lg & 1) << 2;

    const int a_base = (warp_m * 32 + a_row) * 12 + a_col;           // + mt*192
    const int b_base = 2304 + (warp_n * 32 + b_row) * 12 + b_col;    // + w*3072 + p*192 (+1536 lo)

    float acc[3][2][4][4];
    #pragma unroll
    for (int g = 0; g < 3; g++)
        #pragma unroll
        for (int mt = 0; mt < 2; mt++)
            #pragma unroll
            for (int nt = 0; nt < 4; nt++)
                #pragma unroll
                for (int c = 0; c < 4; c++) acc[g][mt][nt][c] = 0.f;

    auto load_stage = [&](int j, int slot) {
        uint32_t base = sb + slot * (STGU * 4);
        int isH = (j < 8);
        int nB = isH ? 1 : 3;
        int koff = isH ? j * 8 : (j - 8) * 8;
        int K2 = isH ? KH2 : KA2;
        const unsigned* Ah = isH ? g_Hh : g_Agh;
        const unsigned* Al = isH ? g_Hl : g_Agl;
        const unsigned* Bsrc = Wimg + (isH ? (size_t)j * 2048
                                           : (size_t)16384 + (size_t)(j - 8) * 6144);
        int nch = 384 + nB * 512;
        for (int c = tid; c < nch; c += 384) {
            uint32_t dst;
            const unsigned* src;
            if (c < 384) {
                int half = (c >= 192) ? 1 : 0;
                int rem = c - half * 192;
                int r = rem >> 1;
                int q = rem & 1;
                int node = row0 + r;
                if (node >= NN) node = NN - 1;
                src = (half ? Al : Ah) + (size_t)node * K2 + koff + q * 4;
                dst = base + (half * 1152 + r * 12 + q * 4) * 4;
            } else {
                int b = c - 384;
                int slotb = b >> 8;          // 0..2nB-1
                int w = slotb >> 1, half = slotb & 1;
                int rem = b & 255;
                int rn = rem >> 1;
                int q = rem & 1;
                src = Bsrc + w * 2048 + half * 1024 + rn * 8 + q * 4;
                dst = base + (2304 + w * 3072 + half * 1536 + rn * 12 + q * 4) * 4;
            }
            cp16(dst, src);
        }
        CP_COMMIT();
    };

    load_stage(0, 0);
    load_stage(1, 1);
    load_stage(2, 2);

    for (int j = 0; j < NJ; j++) {
        CP_WAIT2();
        __syncthreads();
        if (j + 3 < NJ) load_stage(j + 3, (j + 3) & 3);
        else CP_COMMIT();    // keep pending-group count aligned

        const uint32_t st = sb + (j & 3) * (STGU * 4);
        int nB = (j < 8) ? 1 : 3;

        unsigned ah[2][4], al[2][4];
        #pragma unroll
        for (int mt = 0; mt < 2; mt++) {
            uint32_t ad = st + (uint32_t)(a_base + mt * 192) * 4;
            ldsm4(ah[mt][0], ah[mt][1], ah[mt][2], ah[mt][3], ad);
            ldsm4(al[mt][0], al[mt][1], al[mt][2], al[mt][3], ad + 1152 * 4);
        }
        for (int w = 0; w < nB; w++) {
            int g = (j < 8) ? 0 : w;
            uint32_t bd = st + (uint32_t)(b_base + w * 3072) * 4;
            #pragma unroll
            for (int p = 0; p < 2; p++) {
                unsigned bh[4], bl[4];
                uint32_t bp = bd + (uint32_t)(p * 192) * 4;
                ldsm4(bh[0], bh[1], bh[2], bh[3], bp);
                ldsm4(bl[0], bl[1], bl[2], bl[3], bp + 1536 * 4);
                #pragma unroll
                for (int q = 0; q < 2; q++) {
                    int nt = 2 * p + q;
                    #pragma unroll
                    for (int mt = 0; mt < 2; mt++) {
                        mma_bf16(acc[g][mt][nt], ah[mt], &bh[2 * q]);
                        mma_bf16(acc[g][mt][nt], al[mt], &bh[2 * q]);
                        mma_bf16(acc[g][mt][nt], ah[mt], &bl[2 * q]);
                    }
                }
            }
        }
    }

    // ---- epilogue ----
    float dlt = g_delta[0] * (1.f / (float)NN);
    float ampv[2][2], attv[2][2];
    #pragma unroll
    for (int mt = 0; mt < 2; mt++)
        #pragma unroll
        for (int rr = 0; rr < 2; rr++) {
            int row = row0 + warp_m * 32 + mt * 16 + lr + rr * 8;
            float a = 0.f, b = 0.f;
            if (row < NN) {
                float logd = logf((float)g_deg[row] + 1.f);
                a = logd / dlt;
                b = dlt / fmaxf(logd, 1e-5f);
            }
            ampv[mt][rr] = a;
            attv[mt][rr] = b;
        }

    #pragma unroll
    for (int mt = 0; mt < 2; mt++) {
        #pragma unroll
        for (int nt = 0; nt < 4; nt++) {
            int col = warp_n * 32 + nt * 8 + lc * 2;
            float b0 = bias[col], b1 = bias[col + 1];
            #pragma unroll
            for (int rr = 0; rr < 2; rr++) {
                int row = row0 + warp_m * 32 + mt * 16 + lr + rr * 8;
                if (row >= NN) continue;
                float amp = ampv[mt][rr], att = attv[mt][rr];
                int i0 = rr * 2;
                float2 v;
                v.x = fmaxf(acc[0][mt][nt][i0] + amp * acc[1][mt][nt][i0]
                            + att * acc[2][mt][nt][i0] + b0, 0.f);
                v.y = fmaxf(acc[0][mt][nt][i0 + 1] + amp * acc[1][mt][nt][i0 + 1]
                            + att * acc[2][mt][nt][i0 + 1] + b1, 0.f);
                *(float2*)&hout[(size_t)row * DH + col] = v;
                if (write_split) {
                    unsigned hi, lo;
                    split_pair(v.x, v.y, hi, lo);
                    g_Hh[(size_t)row * KH2 + (col >> 1)] = hi;
                    g_Hl[(size_t)row * KH2 + (col >> 1)] = lo;
                }
            }
        }
    }
}

// ---------------- pooling + bn/fc --------------------------------------------
#define POOL_NB 256
__global__ __launch_bounds__(128) void pool_kernel(
        const float* __restrict__ h, const int* __restrict__ batch) {
    int n0 = blockIdx.x * POOL_NB;
    int t = threadIdx.x;
    int nend = min(n0 + POOL_NB, NN);
    int cnt = nend - n0;
    __shared__ int sbm[POOL_NB];
    for (int i = t; i < cnt; i += 128) sbm[i] = batch[n0 + i];
    __syncthreads();
    float acc = 0.f;
    int cur = sbm[0];
    for (int i = 0; i < cnt; i++) {
        int b = sbm[i];
        if (b != cur) {
            atomicAdd(&g_pool[cur * DH + t], acc);
            acc = 0.f; cur = b;
        }
        acc += h[(size_t)(n0 + i) * DH + t];
    }
    atomicAdd(&g_pool[cur * DH + t], acc);
}

__global__ __launch_bounds__(128) void bnfc_kernel(
        const float* __restrict__ gamma, const float* __restrict__ beta,
        const float* __restrict__ fcW, const float* __restrict__ fcb,
        float* __restrict__ out) {
    __shared__ float sp[NG * DH];
    int t = threadIdx.x;
    for (int i = t; i < NG * DH; i += 128) sp[i] = g_pool[i];
    __syncthreads();
    float m = 0.f;
    #pragma unroll 4
    for (int g = 0; g < NG; g++) m += sp[g * DH + t];
    m *= (1.f / NG);
    float v = 0.f;
    #pragma unroll 4
    for (int g = 0; g < NG; g++) { float d = sp[g * DH + t] - m; v += d * d; }
    v *= (1.f / NG);
    float rs = rsqrtf(v + 1e-5f);
    float ga = gamma[t], be = beta[t];
    for (int g = 0; g < NG; g++)
        sp[g * DH + t] = (sp[g * DH + t] - m) * rs * ga + be;
    __syncthreads();
    for (int i = t; i < NG * DLAT; i += 128) {
        int g = i / DLAT, j = i % DLAT;
        float s = fcb[j];
        #pragma unroll 8
        for (int c = 0; c < DH; c++) s += sp[g * DH + c] * fcW[c * DLAT + j];
        out[i] = s;
    }
}

// ---------------- launch ------------------------------------------------------
extern "C" void kernel_launch(void* const* d_in, const int* in_sizes, int n_in,
                              void* d_out, int out_size) {
    const float* x     = (const float*)d_in[0];
    const int*   ei    = (const int*)d_in[1];
    const int*   batch = (const int*)d_in[2];
    const float* W0 = (const float*)d_in[3];  const float* b0 = (const float*)d_in[4];
    const float* W1 = (const float*)d_in[5];  const float* b1 = (const float*)d_in[6];
    const float* W2 = (const float*)d_in[7];  const float* b2 = (const float*)d_in[8];
    const float* gamma = (const float*)d_in[9];
    const float* beta  = (const float*)d_in[10];
    const float* fcW   = (const float*)d_in[11];
    const float* fcb   = (const float*)d_in[12];
    float* out = (float*)d_out;

    void *p_deg, *p_cur, *p_delta, *p_pool, *p_h0, *p_h1, *p_w;
    cudaGetSymbolAddress(&p_deg,   g_deg);
    cudaGetSymbolAddress(&p_cur,   g_cur);
    cudaGetSymbolAddress(&p_delta, g_delta);
    cudaGetSymbolAddress(&p_pool,  g_pool);
    cudaGetSymbolAddress(&p_h0,    g_h0);
    cudaGetSymbolAddress(&p_h1,    g_h1);
    cudaGetSymbolAddress(&p_w,     g_W);
    float* h0 = (float*)p_h0;
    float* h1 = (float*)p_h1;
    unsigned* wimg = (unsigned*)p_w;

    cudaFuncSetAttribute(gemm_fact_kernel,
                         cudaFuncAttributeMaxDynamicSharedMemorySize, SMEM_BYTES);

    cudaMemsetAsync(p_deg,   0, NN * sizeof(int));
    cudaMemsetAsync(p_cur,   0, NN * sizeof(int));
    cudaMemsetAsync(p_delta, 0, sizeof(float));
    cudaMemsetAsync(p_pool,  0, NG * DH * sizeof(float));

    int wthreads = 832 * 128;
    int wblocks = (wthreads + 255) / 256;
    wsplit_kernel<<<wblocks, 256>>>(W0, wimg);
    wsplit_kernel<<<wblocks, 256>>>(W1, wimg + WLAYER);
    wsplit_kernel<<<wblocks, 256>>>(W2, wimg + 2 * WLAYER);
    xsplit_kernel<<<(NN * KH2 + 255) / 256, 256>>>(x);

    int eblocks = (NE + 1023) / 1024;
    int sblocks = (NN + 1023) / 1024;   // 49
    hist_kernel<<<eblocks, 1024>>>(ei);
    scan1_kernel<<<sblocks, 1024>>>();
    scan2_kernel<<<1, 32>>>(sblocks);
    scan3_kernel<<<sblocks, 1024>>>();
    scatter_kernel<<<eblocks, 1024>>>(ei);
    delta_kernel<<<128, 256>>>();

    int gblocks = (NN + BMR - 1) / BMR;   // 521

    agg_kernel<<<NN, 128>>>(x);
    gemm_fact_kernel<<<gblocks, 384, SMEM_BYTES>>>(wimg, b0, h0, 1);
    agg_kernel<<<NN, 128>>>(h0);
    gemm_fact_kernel<<<gblocks, 384, SMEM_BYTES>>>(wimg + WLAYER, b1, h1, 1);
    agg_kernel<<<NN, 128>>>(h1);
    gemm_fact_kernel<<<gblocks, 384, SMEM_BYTES>>>(wimg + 2 * WLAYER, b2, h0, 0);

    pool_kernel<<<(NN + POOL_NB - 1) / POOL_NB, 128>>>(h0, batch);
    bnfc_kernel<<<1, 128>>>(gamma, beta, fcW, fcb, out);
}